// round 3
// baseline (speedup 1.0000x reference)
#include <cuda_runtime.h>
#include <cuda_bf16.h>
#include <math.h>
#include <stdint.h>

// LikelihoodRatioEstimator: N=8192, D=512 fp32 inputs (context, target).
// Outputs 12 fp32 scalars.
//
// Math identities used:
//   logit(i,j) = -log(1 + d2(i,j)),  d2 = max(|c_i|^2 + |t_j|^2 - 2 c_i.t_j, 0)
//   u = 1/(1+d2) = exp(logit)
//   lb = log(S_neg) - log(M), S_neg = sum_offdiag u, a = e^lb = S_neg/M
//   repulsion.mean == 1 exactly; sigmoid(logit-lb) = u/(u+a); (logit-lb)>0 <=> u>a
//
// Precision strategy: Gram matrix in bf16 HMMA (error ~7e-5 per logit, all
// off-diagonal consumers are self-averaging aggregates); the 8192 diagonal
// (positive) elements are computed exactly in fp32 since TP/recall depends on
// borderline threshold compares over only 8192 samples.

#define NN 8192
#define DD 512
#define BM 128
#define BN 128
#define BK 32
#define ROWB 80                    // padded smem row: 32 bf16 = 64B data + 16B pad
#define GEMM_THREADS 256
#define NBX (NN / BN)
#define NBY (NN / BM)
#define NBLK (NBX * NBY)
#define P2_BLOCKS 2048
#define P2_THREADS 256

// Scratch (allocation-free rule: __device__ globals)
__device__ float          g_U[(size_t)NN * (size_t)NN];   // u approx, 268 MB
__device__ __nv_bfloat16  g_Cb[(size_t)NN * DD];
__device__ __nv_bfloat16  g_Tb[(size_t)NN * DD];
__device__ float  g_r2c[NN];
__device__ float  g_r2t[NN];
__device__ float  g_Ud[NN];                   // exact diag u
__device__ float  g_Ld[NN];                   // exact diag log(1+d2)
__device__ double g_pS[NBLK];
__device__ double g_pL[NBLK];
__device__ double g_p2S[P2_BLOCKS];
__device__ unsigned int g_p2C[P2_BLOCKS];
__device__ double g_sc[6];                    // S_all, L_all, S_diagA, L_diagA, a, lb

// ---------------------------------------------------------------------------
// Kernel 0: row norms (fp32), exact diagonal stats, fp32->bf16 conversion.
// One warp per row.
// ---------------------------------------------------------------------------
__global__ void k_prep(const float* __restrict__ C, const float* __restrict__ T)
{
    const int lane = threadIdx.x & 31;
    const int row  = blockIdx.x * 8 + (threadIdx.x >> 5);

    const float4* cp = (const float4*)(C + (size_t)row * DD);
    const float4* tp = (const float4*)(T + (size_t)row * DD);
    __nv_bfloat162* cb = (__nv_bfloat162*)(g_Cb + (size_t)row * DD);
    __nv_bfloat162* tb = (__nv_bfloat162*)(g_Tb + (size_t)row * DD);

    float sc = 0.f, st = 0.f, sd = 0.f;
#pragma unroll
    for (int it = 0; it < 4; ++it) {
        int i = lane + 32 * it;                 // float4 index, 128 per row
        float4 c = cp[i];
        float4 t = tp[i];
        sc += c.x * c.x + c.y * c.y + c.z * c.z + c.w * c.w;
        st += t.x * t.x + t.y * t.y + t.z * t.z + t.w * t.w;
        float dx = c.x - t.x, dy = c.y - t.y, dz = c.z - t.z, dw = c.w - t.w;
        sd += dx * dx + dy * dy + dz * dz + dw * dw;
        cb[i * 2 + 0] = __float22bfloat162_rn(make_float2(c.x, c.y));
        cb[i * 2 + 1] = __float22bfloat162_rn(make_float2(c.z, c.w));
        tb[i * 2 + 0] = __float22bfloat162_rn(make_float2(t.x, t.y));
        tb[i * 2 + 1] = __float22bfloat162_rn(make_float2(t.z, t.w));
    }
#pragma unroll
    for (int o = 16; o > 0; o >>= 1) {
        sc += __shfl_xor_sync(0xffffffffu, sc, o);
        st += __shfl_xor_sync(0xffffffffu, st, o);
        sd += __shfl_xor_sync(0xffffffffu, sd, o);
    }
    if (lane == 0) {
        g_r2c[row] = sc;
        g_r2t[row] = st;
        float v = 1.0f + fmaxf(sd, 0.0f);
        g_Ud[row] = 1.0f / v;         // exact (IEEE div)
        g_Ld[row] = logf(v);          // accurate log for pos stats
    }
}

// ---------------------------------------------------------------------------
// Kernel 1: bf16 HMMA GEMM (c @ t^T) + fused epilogue.
// 128x128 tile, BK=32, 8 warps (2x4), warp tile 64x32, mma.sync m16n8k16.
// ---------------------------------------------------------------------------
__device__ __forceinline__ uint32_t smem_u32(const void* p)
{
    return (uint32_t)__cvta_generic_to_shared(p);
}

__global__ void __launch_bounds__(GEMM_THREADS, 2)
k_gemm()
{
    __shared__ __align__(16) unsigned char As[2][BM * ROWB];
    __shared__ __align__(16) unsigned char Bs[2][BN * ROWB];
    __shared__ double red[GEMM_THREADS];

    const int tid   = threadIdx.x;
    const int lane  = tid & 31;
    const int wid   = tid >> 5;
    const int warpM = wid >> 2;      // 0..1
    const int warpN = wid & 3;       // 0..3
    const int bx = blockIdx.x;
    const int by = blockIdx.y;
    const int rowBase = by * BM;
    const int colBase = bx * BN;

    // ---- global loader mapping: 512 x 16B chunks per matrix per stage ----
    // chunk q: row = q>>2, kchunk = q&3 (16B = 8 bf16)
    const int qr0 = tid >> 2;              // rows 0..63
    const int qc  = (tid & 3) * 8;         // bf16 offset of chunk in k-slice
    const __nv_bfloat16* aG0 = g_Cb + (size_t)(rowBase + qr0)      * DD + qc;
    const __nv_bfloat16* aG1 = g_Cb + (size_t)(rowBase + qr0 + 64) * DD + qc;
    const __nv_bfloat16* bG0 = g_Tb + (size_t)(colBase + qr0)      * DD + qc;
    const __nv_bfloat16* bG1 = g_Tb + (size_t)(colBase + qr0 + 64) * DD + qc;

    const int sOffA0 = qr0 * ROWB + (tid & 3) * 16;
    const int sOffA1 = (qr0 + 64) * ROWB + (tid & 3) * 16;

    // ---- ldmatrix lane addresses ----
    const int aRow = warpM * 64 + (lane & 15);
    const int aCh  = (lane >> 4) * 16;
    const int bRow = warpN * 32 + (lane & 7);
    const int bCh  = ((lane >> 3) & 1) * 16;

    uint32_t aBase0 = smem_u32(&As[0][0]) + aRow * ROWB + aCh;
    uint32_t aBase1 = smem_u32(&As[1][0]) + aRow * ROWB + aCh;
    uint32_t bBase0 = smem_u32(&Bs[0][0]) + bRow * ROWB + bCh;
    uint32_t bBase1 = smem_u32(&Bs[1][0]) + bRow * ROWB + bCh;

    float acc[4][4][4];
#pragma unroll
    for (int mf = 0; mf < 4; ++mf)
#pragma unroll
        for (int nf = 0; nf < 4; ++nf)
#pragma unroll
            for (int e = 0; e < 4; ++e) acc[mf][nf][e] = 0.f;

    // prologue: stage 0
    {
        uint4 a0 = *(const uint4*)aG0;
        uint4 a1 = *(const uint4*)aG1;
        uint4 b0 = *(const uint4*)bG0;
        uint4 b1 = *(const uint4*)bG1;
        *(uint4*)(&As[0][sOffA0]) = a0;
        *(uint4*)(&As[0][sOffA1]) = a1;
        *(uint4*)(&Bs[0][sOffA0]) = b0;
        *(uint4*)(&Bs[0][sOffA1]) = b1;
    }
    __syncthreads();

    const int KT = DD / BK;   // 16 stages
    int buf = 0;
    for (int kt = 0; kt < KT; ++kt) {
        uint4 pa0, pa1, pb0, pb1;
        if (kt + 1 < KT) {
            const int off = (kt + 1) * BK;
            pa0 = *(const uint4*)(aG0 + off);
            pa1 = *(const uint4*)(aG1 + off);
            pb0 = *(const uint4*)(bG0 + off);
            pb1 = *(const uint4*)(bG1 + off);
        }

        const uint32_t aB = buf ? aBase1 : aBase0;
        const uint32_t bB = buf ? bBase1 : bBase0;

#pragma unroll
        for (int ks = 0; ks < 2; ++ks) {
            uint32_t afr[4][4];
            uint32_t bfr[4][2];
#pragma unroll
            for (int mf = 0; mf < 4; ++mf) {
                uint32_t addr = aB + mf * (16 * ROWB) + ks * 32;
                asm volatile(
                    "ldmatrix.sync.aligned.m8n8.x4.shared.b16 {%0,%1,%2,%3}, [%4];"
                    : "=r"(afr[mf][0]), "=r"(afr[mf][1]),
                      "=r"(afr[mf][2]), "=r"(afr[mf][3])
                    : "r"(addr));
            }
#pragma unroll
            for (int nf = 0; nf < 4; ++nf) {
                uint32_t addr = bB + nf * (8 * ROWB) + ks * 32;
                asm volatile(
                    "ldmatrix.sync.aligned.m8n8.x2.shared.b16 {%0,%1}, [%2];"
                    : "=r"(bfr[nf][0]), "=r"(bfr[nf][1])
                    : "r"(addr));
            }
#pragma unroll
            for (int mf = 0; mf < 4; ++mf)
#pragma unroll
                for (int nf = 0; nf < 4; ++nf) {
                    asm volatile(
                        "mma.sync.aligned.m16n8k16.row.col.f32.bf16.bf16.f32 "
                        "{%0,%1,%2,%3}, {%4,%5,%6,%7}, {%8,%9}, {%0,%1,%2,%3};"
                        : "+f"(acc[mf][nf][0]), "+f"(acc[mf][nf][1]),
                          "+f"(acc[mf][nf][2]), "+f"(acc[mf][nf][3])
                        : "r"(afr[mf][0]), "r"(afr[mf][1]),
                          "r"(afr[mf][2]), "r"(afr[mf][3]),
                          "r"(bfr[nf][0]), "r"(bfr[nf][1]));
                }
        }

        if (kt + 1 < KT) {
            const int nb = buf ^ 1;
            *(uint4*)(&As[nb][sOffA0]) = pa0;
            *(uint4*)(&As[nb][sOffA1]) = pa1;
            *(uint4*)(&Bs[nb][sOffA0]) = pb0;
            *(uint4*)(&Bs[nb][sOffA1]) = pb1;
            __syncthreads();
            buf = nb;
        }
    }

    // ---- epilogue: u = 1/(1+d2), sums of u and log(1+d2), store u ----
    float sU = 0.f, sL = 0.f;
#pragma unroll
    for (int mf = 0; mf < 4; ++mf) {
        const int r0 = rowBase + warpM * 64 + mf * 16 + (lane >> 2);
        const int r1 = r0 + 8;
        const float r2a = g_r2c[r0];
        const float r2b = g_r2c[r1];
#pragma unroll
        for (int nf = 0; nf < 4; ++nf) {
            const int c0 = colBase + warpN * 32 + nf * 8 + 2 * (lane & 3);
            const float q0 = g_r2t[c0];
            const float q1 = g_r2t[c0 + 1];

            float d00 = fmaxf(r2a + q0 - 2.0f * acc[mf][nf][0], 0.0f);
            float d01 = fmaxf(r2a + q1 - 2.0f * acc[mf][nf][1], 0.0f);
            float d10 = fmaxf(r2b + q0 - 2.0f * acc[mf][nf][2], 0.0f);
            float d11 = fmaxf(r2b + q1 - 2.0f * acc[mf][nf][3], 0.0f);

            float v00 = 1.0f + d00, v01 = 1.0f + d01;
            float v10 = 1.0f + d10, v11 = 1.0f + d11;
            float u00 = __frcp_rn(v00), u01 = __frcp_rn(v01);
            float u10 = __frcp_rn(v10), u11 = __frcp_rn(v11);
            sU += (u00 + u01) + (u10 + u11);
            sL += (__logf(v00) + __logf(v01)) + (__logf(v10) + __logf(v11));

            *(float2*)(g_U + (size_t)r0 * NN + c0) = make_float2(u00, u01);
            *(float2*)(g_U + (size_t)r1 * NN + c0) = make_float2(u10, u11);
        }
    }

    // deterministic block reduction (double)
    red[tid] = (double)sU;
    __syncthreads();
#pragma unroll
    for (int s = GEMM_THREADS / 2; s > 0; s >>= 1) {
        if (tid < s) red[tid] += red[tid + s];
        __syncthreads();
    }
    if (tid == 0) g_pS[by * NBX + bx] = red[0];
    __syncthreads();

    red[tid] = (double)sL;
    __syncthreads();
#pragma unroll
    for (int s = GEMM_THREADS / 2; s > 0; s >>= 1) {
        if (tid < s) red[tid] += red[tid + s];
        __syncthreads();
    }
    if (tid == 0) g_pL[by * NBX + bx] = red[0];
}

// ---------------------------------------------------------------------------
// Kernel 2: reduce pass-1 partials + APPROX diagonal sums; compute a and lb.
// ---------------------------------------------------------------------------
__global__ void k_reduce1()
{
    __shared__ double sh[256];
    const int tid = threadIdx.x;

    double vS = 0.0, vL = 0.0, vSd = 0.0, vLd = 0.0;
    for (int b = tid; b < NBLK; b += 256) { vS += g_pS[b]; vL += g_pL[b]; }
    for (int i = tid; i < NN; i += 256) {
        float ua = g_U[(size_t)i * NN + i];       // approx diag u
        vSd += (double)ua;
        vLd += (double)(-__logf(ua));             // approx diag log(1+d2)
    }

    double vals[4] = {vS, vL, vSd, vLd};
    double outv[4];
#pragma unroll
    for (int q = 0; q < 4; ++q) {
        sh[tid] = vals[q];
        __syncthreads();
        for (int s = 128; s > 0; s >>= 1) {
            if (tid < s) sh[tid] += sh[tid + s];
            __syncthreads();
        }
        outv[q] = sh[0];
        __syncthreads();
    }

    if (tid == 0) {
        const double M = (double)NN * (double)(NN - 1);
        const double S_neg = outv[0] - outv[2];
        g_sc[0] = outv[0];
        g_sc[1] = outv[1];
        g_sc[2] = outv[2];
        g_sc[3] = outv[3];
        g_sc[4] = S_neg / M;              // a = e^lb
        g_sc[5] = log(S_neg) - log(M);    // lb
    }
}

// ---------------------------------------------------------------------------
// Kernel 3: pass 2 over g_U: sum u/(u+a), count u>a (all N^2 elements).
// ---------------------------------------------------------------------------
__global__ void __launch_bounds__(P2_THREADS)
k_pass2()
{
    __shared__ double shS[P2_THREADS];
    __shared__ unsigned int shC[P2_THREADS];

    const float a = (float)g_sc[4];
    const size_t stride = (size_t)gridDim.x * blockDim.x;
    size_t idx = (size_t)blockIdx.x * blockDim.x + threadIdx.x;
    const float4* U4 = (const float4*)g_U;
    const size_t n4 = ((size_t)NN * (size_t)NN) / 4;

    float fs = 0.f;
    unsigned int cnt = 0;
    for (size_t i = idx; i < n4; i += stride) {
        float4 u = U4[i];
        fs += __fdividef(u.x, u.x + a);
        fs += __fdividef(u.y, u.y + a);
        fs += __fdividef(u.z, u.z + a);
        fs += __fdividef(u.w, u.w + a);
        cnt += (unsigned)(u.x > a) + (unsigned)(u.y > a)
             + (unsigned)(u.z > a) + (unsigned)(u.w > a);
    }

    shS[threadIdx.x] = (double)fs;
    shC[threadIdx.x] = cnt;
    __syncthreads();
    for (int s = P2_THREADS / 2; s > 0; s >>= 1) {
        if (threadIdx.x < s) {
            shS[threadIdx.x] += shS[threadIdx.x + s];
            shC[threadIdx.x] += shC[threadIdx.x + s];
        }
        __syncthreads();
    }
    if (threadIdx.x == 0) {
        g_p2S[blockIdx.x] = shS[0];
        g_p2C[blockIdx.x] = shC[0];
    }
}

// ---------------------------------------------------------------------------
// Kernel 4: final reduce + 12 outputs.
// Off-diagonal stats: pass2 totals minus APPROX diagonal contributions.
// Positive (diagonal) stats: EXACT fp32 diagonal from k_prep.
// ---------------------------------------------------------------------------
__global__ void k_final(float* __restrict__ out)
{
    __shared__ double sh[256];
    const int tid = threadIdx.x;
    const double a  = g_sc[4];
    const double lb = g_sc[5];
    const float  af = (float)a;   // same rounding as pass 2 for count consistency

    double vS = 0.0, vC = 0.0;            // pass2 totals
    double vSdA = 0.0, vCdA = 0.0;        // approx diag sigmoid-sum / count
    double vLdE = 0.0, vSdE = 0.0, vCdE = 0.0;  // exact diag stats
    for (int b = tid; b < P2_BLOCKS; b += 256) {
        vS += g_p2S[b];
        vC += (double)g_p2C[b];
    }
    for (int i = tid; i < NN; i += 256) {
        float ua = g_U[(size_t)i * NN + i];      // approx diag (as seen by pass2)
        double uda = (double)ua;
        vSdA += uda / (uda + a);
        if (ua > af) vCdA += 1.0;

        float ue = g_Ud[i];                      // exact diag
        double ude = (double)ue;
        vLdE += (double)g_Ld[i];
        vSdE += ude / (ude + a);
        if ((double)ue > a) vCdE += 1.0;
    }

    double vals[7] = {vS, vC, vSdA, vCdA, vLdE, vSdE, vCdE};
    double o[7];
#pragma unroll
    for (int q = 0; q < 7; ++q) {
        sh[tid] = vals[q];
        __syncthreads();
        for (int s = 128; s > 0; s >>= 1) {
            if (tid < s) sh[tid] += sh[tid + s];
            __syncthreads();
        }
        o[q] = sh[0];
        __syncthreads();
    }

    if (tid == 0) {
        const double S_all = o[0], C_all = o[1];
        const double S_dA = o[2], C_dA = o[3];
        const double L_dE = o[4], S_dE = o[5], C_dE = o[6];
        const double L_all = g_sc[1], L_dA = g_sc[3];
        const double M  = (double)NN * (double)(NN - 1);
        const double Nd = (double)NN;

        const double pos_mean = -L_dE / Nd - lb;
        const double neg_mean = -(L_all - L_dA) / M - lb;
        const double loss     = 1.0 - pos_mean;      // repulsion.mean == 1 exactly
        const double sig_pos  = S_dE / Nd;
        const double sig_neg  = (S_all - S_dA) / M;

        const double TP = C_dE / Nd;
        const double FP = (C_all - C_dA) / M;
        const double TN = 1.0 - FP;
        const double FN = 1.0 - TP;
        const double accuracy  = 0.5 * (TP + TN);
        const double precision = TP / (TP + FP);
        const double npv       = TN / (TN + FN);
        const double apv       = 0.5 * (precision + npv);

        out[0]  = (float)loss;
        out[1]  = (float)pos_mean;
        out[2]  = (float)neg_mean;
        out[3]  = (float)sig_pos;
        out[4]  = (float)sig_neg;
        out[5]  = (float)lb;
        out[6]  = (float)accuracy;
        out[7]  = (float)precision;
        out[8]  = (float)npv;
        out[9]  = (float)apv;
        out[10] = (float)TP;
        out[11] = (float)TN;
    }
}

// ---------------------------------------------------------------------------
extern "C" void kernel_launch(void* const* d_in, const int* in_sizes, int n_in,
                              void* d_out, int out_size)
{
    const float* C = (const float*)d_in[0];
    const float* T = (const float*)d_in[1];
    float* out = (float*)d_out;
    (void)in_sizes; (void)n_in; (void)out_size;

    k_prep<<<NN / 8, 256>>>(C, T);
    k_gemm<<<dim3(NBX, NBY), GEMM_THREADS>>>();
    k_reduce1<<<1, 256>>>();
    k_pass2<<<P2_BLOCKS, P2_THREADS>>>();
    k_final<<<1, 256>>>(out);
}